// round 1
// baseline (speedup 1.0000x reference)
#include <cuda_runtime.h>
#include <cuda_bf16.h>
#include <mma.h>
#include <math.h>

using namespace nvcuda;

// ---------------- constants ----------------
#define SEQ      2048
#define DMODEL   2048
#define HEADS    16
#define HDIM     128
#define INNER    8192
#define LN_EPS   1e-5f

// ---------------- scratch (static device memory; no allocations) ----------
__device__ float g_c[SEQ * 3 * DMODEL];     // QKV
__device__ float g_attn[SEQ * DMODEL];      // attention output (pre-proj)
__device__ float g_res1[SEQ * DMODEL];      // x + proj(attn)
__device__ float g_h1[SEQ * DMODEL];        // LN1 output
__device__ float g_ff[SEQ * INNER];         // gelu(h1@ff1+b)
__device__ float g_res2[SEQ * DMODEL];      // h1 + ff2 out

// ---------------- helpers ----------------
__device__ __forceinline__ float gelu_f(float v) {
    return 0.5f * v * (1.0f + erff(v * 0.7071067811865476f));
}

// ================= TF32 WMMA GEMM, 128x128x32 tiles, fused epilogue =========
// C[M,N] = A[M,K] @ B[K,N] + bias ; optional residual add / gelu.
// M,N,K all multiples of 128/32 for this problem, no bounds checks.
#define ALD 36    // A smem leading dim (128 x 32 tile)
#define BLD 132   // B smem leading dim (32 x 128 tile)

enum { EPI_BIAS = 0, EPI_BIAS_RES = 1, EPI_BIAS_GELU = 2 };

template <int EPI>
__global__ void __launch_bounds__(256)
gemm_tf32(const float* __restrict__ A, const float* __restrict__ B,
          const float* __restrict__ bias, const float* __restrict__ res,
          float* __restrict__ C, int M, int N, int K)
{
    extern __shared__ float sm[];
    float* As = sm;               // 128 x ALD
    float* Bs = sm + 128 * ALD;   // 32 x BLD

    const int tid  = threadIdx.x;
    const int bm   = blockIdx.y;
    const int bn   = blockIdx.x;
    const int warp = tid >> 5;
    const int wm   = warp & 3;    // 4 warps along M -> 32 rows each
    const int wn   = warp >> 2;   // 2 warps along N -> 64 cols each

    wmma::fragment<wmma::accumulator, 16, 16, 8, float> cf[2][4];
    #pragma unroll
    for (int i = 0; i < 2; ++i)
        #pragma unroll
        for (int j = 0; j < 4; ++j)
            wmma::fill_fragment(cf[i][j], 0.0f);

    const int kTiles = K >> 5;  // K / 32
    for (int kt = 0; kt < kTiles; ++kt) {
        __syncthreads();
        // load A tile 128x32 (row-major), convert to tf32 at store
        #pragma unroll
        for (int i = 0; i < 4; ++i) {
            int idx = tid + i * 256;            // 1024 float4
            int r = idx >> 3, c4 = idx & 7;
            float4 v = *(const float4*)(A + (size_t)(bm * 128 + r) * K + kt * 32 + c4 * 4);
            v.x = wmma::__float_to_tf32(v.x);
            v.y = wmma::__float_to_tf32(v.y);
            v.z = wmma::__float_to_tf32(v.z);
            v.w = wmma::__float_to_tf32(v.w);
            *(float4*)(As + r * ALD + c4 * 4) = v;
        }
        // load B tile 32x128 (row-major)
        #pragma unroll
        for (int i = 0; i < 4; ++i) {
            int idx = tid + i * 256;
            int r = idx >> 5, c4 = idx & 31;
            float4 v = *(const float4*)(B + (size_t)(kt * 32 + r) * N + bn * 128 + c4 * 4);
            v.x = wmma::__float_to_tf32(v.x);
            v.y = wmma::__float_to_tf32(v.y);
            v.z = wmma::__float_to_tf32(v.z);
            v.w = wmma::__float_to_tf32(v.w);
            *(float4*)(Bs + r * BLD + c4 * 4) = v;
        }
        __syncthreads();

        #pragma unroll
        for (int ks = 0; ks < 4; ++ks) {
            wmma::fragment<wmma::matrix_a, 16, 16, 8, wmma::precision::tf32, wmma::row_major> af[2];
            wmma::fragment<wmma::matrix_b, 16, 16, 8, wmma::precision::tf32, wmma::row_major> bf[4];
            #pragma unroll
            for (int i = 0; i < 2; ++i)
                wmma::load_matrix_sync(af[i], As + (wm * 32 + i * 16) * ALD + ks * 8, ALD);
            #pragma unroll
            for (int j = 0; j < 4; ++j)
                wmma::load_matrix_sync(bf[j], Bs + (ks * 8) * BLD + wn * 64 + j * 16, BLD);
            #pragma unroll
            for (int i = 0; i < 2; ++i)
                #pragma unroll
                for (int j = 0; j < 4; ++j)
                    wmma::mma_sync(cf[i][j], af[i], bf[j], cf[i][j]);
        }
    }

    __syncthreads();
    float* Cs = sm;  // reuse smem: 128 x 128
    #pragma unroll
    for (int i = 0; i < 2; ++i)
        #pragma unroll
        for (int j = 0; j < 4; ++j)
            wmma::store_matrix_sync(Cs + (wm * 32 + i * 16) * 128 + wn * 64 + j * 16,
                                    cf[i][j], 128, wmma::mem_row_major);
    __syncthreads();

    #pragma unroll
    for (int it = 0; it < 16; ++it) {
        int f4 = tid + it * 256;        // 4096 float4 in tile
        int r = f4 >> 5, c4 = f4 & 31;
        float4 v = ((float4*)Cs)[f4];
        int gn = bn * 128 + c4 * 4;
        float4 bv = *(const float4*)(bias + gn);
        v.x += bv.x; v.y += bv.y; v.z += bv.z; v.w += bv.w;
        size_t goff = (size_t)(bm * 128 + r) * N + gn;
        if (EPI == EPI_BIAS_RES) {
            float4 rv = *(const float4*)(res + goff);
            v.x += rv.x; v.y += rv.y; v.z += rv.z; v.w += rv.w;
        }
        if (EPI == EPI_BIAS_GELU) {
            v.x = gelu_f(v.x); v.y = gelu_f(v.y);
            v.z = gelu_f(v.z); v.w = gelu_f(v.w);
        }
        *(float4*)(C + goff) = v;
    }
}

// ================= causal flash attention, fp32 ============================
// c layout: [SEQ, 3*DMODEL] rows = [q | k | v], head h at cols h*128.
// Block: (qt, h). BQ=BK=64, 256 threads.
// Thread t owns q row t/4, d-quarter (t%4)*32 of the O accumulator.
#define ATT_SMEM ((3 * 64 * 128 + 64 * 64 + 3 * 64) * 4)

__global__ void __launch_bounds__(256)
attn_kernel(const float* __restrict__ c, float* __restrict__ out)
{
    const int h  = blockIdx.y;
    const int qt = gridDim.x - 1 - blockIdx.x;   // heavy tiles launched first

    extern __shared__ float smem[];
    float* Qs   = smem;               // 64 x 128
    float* Ks   = Qs + 64 * 128;      // 64 x 128
    float* Vs   = Ks + 64 * 128;      // 64 x 128
    float* S    = Vs + 64 * 128;      // 64 x 64
    float* mrow = S + 64 * 64;        // 64
    float* lrow = mrow + 64;          // 64
    float* arow = lrow + 64;          // 64

    const int tid  = threadIdx.x;
    const int qr   = tid >> 2;        // 0..63
    const int quad = tid & 3;         // d quarter / k segment

    // load Q tile
    #pragma unroll
    for (int i = 0; i < 8; ++i) {
        int idx = tid + i * 256;      // 2048 float4
        int r = idx >> 5, c4 = idx & 31;
        ((float4*)Qs)[idx] =
            *(const float4*)(c + (size_t)(qt * 64 + r) * (3 * DMODEL) + h * HDIM + c4 * 4);
    }
    if (tid < 64) { mrow[tid] = -1e30f; lrow[tid] = 0.0f; }

    float acc[32];
    #pragma unroll
    for (int i = 0; i < 32; ++i) acc[i] = 0.0f;

    const float scale = 0.022097086912079608f;  // 1/sqrt(2048)

    for (int j = 0; j <= qt; ++j) {
        __syncthreads();
        // load K, V tiles
        #pragma unroll
        for (int i = 0; i < 8; ++i) {
            int idx = tid + i * 256;
            int r = idx >> 5, c4 = idx & 31;
            size_t base = (size_t)(j * 64 + r) * (3 * DMODEL) + h * HDIM + c4 * 4;
            ((float4*)Ks)[idx] = *(const float4*)(c + base + DMODEL);
            ((float4*)Vs)[idx] = *(const float4*)(c + base + 2 * DMODEL);
        }
        __syncthreads();

        // scores: thread computes S[qr][quad*16 .. quad*16+15]
        float sreg[16];
        #pragma unroll
        for (int kk = 0; kk < 16; ++kk) sreg[kk] = 0.0f;
        #pragma unroll 4
        for (int x = 0; x < 32; ++x) {
            float4 q4 = ((float4*)Qs)[qr * 32 + x];
            #pragma unroll
            for (int kk = 0; kk < 16; ++kk) {
                float4 k4 = ((float4*)Ks)[(quad * 16 + kk) * 32 + x];
                sreg[kk] += q4.x * k4.x + q4.y * k4.y + q4.z * k4.z + q4.w * k4.w;
            }
        }
        const bool diag = (j == qt);
        #pragma unroll
        for (int kk = 0; kk < 16; ++kk) {
            int kr = quad * 16 + kk;
            float v = sreg[kk] * scale;
            if (diag && kr > qr) v = -1e30f;
            S[qr * 64 + kr] = v;
        }
        __syncthreads();

        // online softmax per row (threads 0..63)
        if (tid < 64) {
            float m_old = mrow[tid];
            float mx = m_old;
            #pragma unroll 8
            for (int k = 0; k < 64; ++k) mx = fmaxf(mx, S[tid * 64 + k]);
            float alpha = __expf(m_old - mx);
            float sum = 0.0f;
            #pragma unroll 8
            for (int k = 0; k < 64; ++k) {
                float p = __expf(S[tid * 64 + k] - mx);
                S[tid * 64 + k] = p;
                sum += p;
            }
            mrow[tid] = mx;
            lrow[tid] = lrow[tid] * alpha + sum;
            arow[tid] = alpha;
        }
        __syncthreads();

        // rescale + accumulate P @ V
        float alpha = arow[qr];
        #pragma unroll
        for (int i = 0; i < 32; ++i) acc[i] *= alpha;
        for (int kr = 0; kr < 64; ++kr) {
            float p = S[qr * 64 + kr];
            #pragma unroll
            for (int d4 = 0; d4 < 8; ++d4) {
                float4 v4 = ((float4*)Vs)[kr * 32 + quad * 8 + d4];
                acc[d4 * 4 + 0] += p * v4.x;
                acc[d4 * 4 + 1] += p * v4.y;
                acc[d4 * 4 + 2] += p * v4.z;
                acc[d4 * 4 + 3] += p * v4.w;
            }
        }
    }
    __syncthreads();

    float linv = 1.0f / lrow[qr];
    #pragma unroll
    for (int d4 = 0; d4 < 8; ++d4) {
        float4 o;
        o.x = acc[d4 * 4 + 0] * linv;
        o.y = acc[d4 * 4 + 1] * linv;
        o.z = acc[d4 * 4 + 2] * linv;
        o.w = acc[d4 * 4 + 3] * linv;
        *(float4*)(out + (size_t)(qt * 64 + qr) * DMODEL + h * HDIM + quad * 32 + d4 * 4) = o;
    }
}

// ================= LayerNorm: one block per row =============================
__global__ void __launch_bounds__(256)
ln_kernel(const float* __restrict__ in, const float* __restrict__ g,
          const float* __restrict__ b, float* __restrict__ out)
{
    const int row = blockIdx.x;
    const int tid = threadIdx.x;
    const float4* x4 = (const float4*)(in + (size_t)row * DMODEL);

    float4 v0 = x4[tid];
    float4 v1 = x4[tid + 256];
    float s = v0.x + v0.y + v0.z + v0.w + v1.x + v1.y + v1.z + v1.w;
    float q = v0.x * v0.x + v0.y * v0.y + v0.z * v0.z + v0.w * v0.w
            + v1.x * v1.x + v1.y * v1.y + v1.z * v1.z + v1.w * v1.w;

    #pragma unroll
    for (int o = 16; o > 0; o >>= 1) {
        s += __shfl_down_sync(0xffffffffu, s, o);
        q += __shfl_down_sync(0xffffffffu, q, o);
    }
    __shared__ float rs[8], rq[8], fin[2];
    if ((tid & 31) == 0) { rs[tid >> 5] = s; rq[tid >> 5] = q; }
    __syncthreads();
    if (tid == 0) {
        float S = 0.0f, Q = 0.0f;
        #pragma unroll
        for (int i = 0; i < 8; ++i) { S += rs[i]; Q += rq[i]; }
        float mu  = S * (1.0f / DMODEL);
        float var = Q * (1.0f / DMODEL) - mu * mu;
        fin[0] = mu;
        fin[1] = rsqrtf(var + LN_EPS);
    }
    __syncthreads();
    float mu = fin[0], r = fin[1];

    float4 g0 = ((const float4*)g)[tid], g1 = ((const float4*)g)[tid + 256];
    float4 b0 = ((const float4*)b)[tid], b1 = ((const float4*)b)[tid + 256];
    float4 o0, o1;
    o0.x = (v0.x - mu) * r * g0.x + b0.x;
    o0.y = (v0.y - mu) * r * g0.y + b0.y;
    o0.z = (v0.z - mu) * r * g0.z + b0.z;
    o0.w = (v0.w - mu) * r * g0.w + b0.w;
    o1.x = (v1.x - mu) * r * g1.x + b1.x;
    o1.y = (v1.y - mu) * r * g1.y + b1.y;
    o1.z = (v1.z - mu) * r * g1.z + b1.z;
    o1.w = (v1.w - mu) * r * g1.w + b1.w;
    ((float4*)(out + (size_t)row * DMODEL))[tid]       = o0;
    ((float4*)(out + (size_t)row * DMODEL))[tid + 256] = o1;
}

// ================= launch ===================================================
extern "C" void kernel_launch(void* const* d_in, const int* in_sizes, int n_in,
                              void* d_out, int out_size)
{
    (void)in_sizes; (void)n_in; (void)out_size;

    const float* x     = (const float*)d_in[0];
    const float* C_w   = (const float*)d_in[1];
    const float* C_b   = (const float*)d_in[2];
    const float* lin_w = (const float*)d_in[3];
    const float* lin_b = (const float*)d_in[4];
    const float* ff1_w = (const float*)d_in[5];
    const float* ff1_b = (const float*)d_in[6];
    const float* ff2_w = (const float*)d_in[7];
    const float* ff2_b = (const float*)d_in[8];
    const float* ln1_g = (const float*)d_in[9];
    const float* ln1_b = (const float*)d_in[10];
    const float* ln2_g = (const float*)d_in[11];
    const float* ln2_b = (const float*)d_in[12];
    float* out = (float*)d_out;

    float *c, *attn, *res1, *h1, *ff, *res2;
    cudaGetSymbolAddress((void**)&c,    g_c);
    cudaGetSymbolAddress((void**)&attn, g_attn);
    cudaGetSymbolAddress((void**)&res1, g_res1);
    cudaGetSymbolAddress((void**)&h1,   g_h1);
    cudaGetSymbolAddress((void**)&ff,   g_ff);
    cudaGetSymbolAddress((void**)&res2, g_res2);

    const size_t gsm = 128 * 128 * sizeof(float);  // 64KB for gemm
    cudaFuncSetAttribute(gemm_tf32<EPI_BIAS>,      cudaFuncAttributeMaxDynamicSharedMemorySize, gsm);
    cudaFuncSetAttribute(gemm_tf32<EPI_BIAS_RES>,  cudaFuncAttributeMaxDynamicSharedMemorySize, gsm);
    cudaFuncSetAttribute(gemm_tf32<EPI_BIAS_GELU>, cudaFuncAttributeMaxDynamicSharedMemorySize, gsm);
    cudaFuncSetAttribute(attn_kernel,              cudaFuncAttributeMaxDynamicSharedMemorySize, ATT_SMEM);

    dim3 blk(256);

    // 1) QKV: c = x @ C_w + C_b          [2048, 6144]
    gemm_tf32<EPI_BIAS><<<dim3(3 * DMODEL / 128, SEQ / 128), blk, gsm>>>(
        x, C_w, C_b, nullptr, c, SEQ, 3 * DMODEL, DMODEL);

    // 2) causal attention -> attn        [2048, 2048]
    attn_kernel<<<dim3(SEQ / 64, HEADS), 256, ATT_SMEM>>>(c, attn);

    // 3) res1 = x + attn @ lin_w + lin_b
    gemm_tf32<EPI_BIAS_RES><<<dim3(DMODEL / 128, SEQ / 128), blk, gsm>>>(
        attn, lin_w, lin_b, x, res1, SEQ, DMODEL, DMODEL);

    // 4) h1 = LN1(res1)
    ln_kernel<<<SEQ, 256>>>(res1, ln1_g, ln1_b, h1);

    // 5) ff = gelu(h1 @ ff1_w + ff1_b)   [2048, 8192]
    gemm_tf32<EPI_BIAS_GELU><<<dim3(INNER / 128, SEQ / 128), blk, gsm>>>(
        h1, ff1_w, ff1_b, nullptr, ff, SEQ, INNER, DMODEL);

    // 6) res2 = h1 + ff @ ff2_w + ff2_b
    gemm_tf32<EPI_BIAS_RES><<<dim3(DMODEL / 128, SEQ / 128), blk, gsm>>>(
        ff, ff2_w, ff2_b, h1, res2, SEQ, DMODEL, INNER);

    // 7) out = LN2(res2)
    ln_kernel<<<SEQ, 256>>>(res2, ln2_g, ln2_b, out);
}

// round 2
// speedup vs baseline: 2.1361x; 2.1361x over previous
#include <cuda_runtime.h>
#include <cuda_bf16.h>
#include <mma.h>
#include <math.h>

using namespace nvcuda;

// ---------------- constants ----------------
#define SEQ      2048
#define DMODEL   2048
#define HEADS    16
#define HDIM     128
#define INNER    8192
#define LN_EPS   1e-5f

// ---------------- scratch (static device memory; no allocations) ----------
__device__ float g_c[SEQ * 3 * DMODEL];     // QKV
__device__ float g_attn[SEQ * DMODEL];      // attention output (pre-proj)
__device__ float g_res1[SEQ * DMODEL];      // x + proj(attn)
__device__ float g_h1[SEQ * DMODEL];        // LN1 output
__device__ float g_ff[SEQ * INNER];         // gelu(h1@ff1+b)
__device__ float g_res2[SEQ * DMODEL];      // h1 + ff2 out

// ---------------- helpers ----------------
__device__ __forceinline__ float gelu_f(float v) {
    return 0.5f * v * (1.0f + erff(v * 0.7071067811865476f));
}
__device__ __forceinline__ float4 tf32x4(float4 v) {
    v.x = wmma::__float_to_tf32(v.x);
    v.y = wmma::__float_to_tf32(v.y);
    v.z = wmma::__float_to_tf32(v.z);
    v.w = wmma::__float_to_tf32(v.w);
    return v;
}

// ================= TF32 WMMA GEMM, 128x128x32 tiles ========================
// Register-staged double-buffered pipeline: LDG(k+1) issued before MMA(k),
// convert+STS after MMA, one __syncthreads per k-tile.
#define ALD 36    // A smem leading dim (128 x 32 tile)
#define BLD 132   // B smem leading dim (32 x 128 tile)

enum { EPI_BIAS = 0, EPI_BIAS_RES = 1, EPI_BIAS_GELU = 2 };

template <int EPI>
__global__ void __launch_bounds__(256)
gemm_tf32(const float* __restrict__ A, const float* __restrict__ B,
          const float* __restrict__ bias, const float* __restrict__ res,
          float* __restrict__ C, int M, int N, int K)
{
    extern __shared__ float sm[];
    float* As = sm;                       // [2][128*ALD]
    float* Bs = sm + 2 * 128 * ALD;       // [2][32*BLD]

    const int tid  = threadIdx.x;
    const int bm   = blockIdx.y;
    const int bn   = blockIdx.x;
    const int warp = tid >> 5;
    const int wm   = warp & 3;    // 4 warps along M -> 32 rows each
    const int wn   = warp >> 2;   // 2 warps along N -> 64 cols each

    wmma::fragment<wmma::accumulator, 16, 16, 8, float> cf[2][4];
    #pragma unroll
    for (int i = 0; i < 2; ++i)
        #pragma unroll
        for (int j = 0; j < 4; ++j)
            wmma::fill_fragment(cf[i][j], 0.0f);

    // per-thread staging registers
    float4 ra[4], rb[4];
    const int arow_ = tid >> 3, ac4 = (tid & 7) * 4;       // A: 8 f4 per row
    const int brow_ = tid >> 5, bc4 = (tid & 31) * 4;      // B: 32 f4 per row
    const float* Aptr = A + (size_t)(bm * 128) * K;
    const float* Bptr = B + (size_t)bn * 128;

    const int kTiles = K >> 5;

    // prologue: load + stage tile 0
    #pragma unroll
    for (int i = 0; i < 4; ++i)
        ra[i] = *(const float4*)(Aptr + (size_t)(arow_ + i * 32) * K + ac4);
    #pragma unroll
    for (int i = 0; i < 4; ++i)
        rb[i] = *(const float4*)(Bptr + (size_t)(brow_ + i * 8) * N + bc4);
    #pragma unroll
    for (int i = 0; i < 4; ++i)
        *(float4*)(As + (arow_ + i * 32) * ALD + ac4) = tf32x4(ra[i]);
    #pragma unroll
    for (int i = 0; i < 4; ++i)
        *(float4*)(Bs + (brow_ + i * 8) * BLD + bc4) = tf32x4(rb[i]);
    __syncthreads();

    for (int kt = 0; kt < kTiles; ++kt) {
        // issue loads for next tile (latency hidden behind MMAs)
        if (kt + 1 < kTiles) {
            #pragma unroll
            for (int i = 0; i < 4; ++i)
                ra[i] = *(const float4*)(Aptr + (size_t)(arow_ + i * 32) * K
                                          + (kt + 1) * 32 + ac4);
            #pragma unroll
            for (int i = 0; i < 4; ++i)
                rb[i] = *(const float4*)(Bptr + (size_t)((kt + 1) * 32 + brow_ + i * 8) * N + bc4);
        }

        const float* Ab = As + (kt & 1) * 128 * ALD;
        const float* Bb = Bs + (kt & 1) * 32 * BLD;
        #pragma unroll
        for (int ks = 0; ks < 4; ++ks) {
            wmma::fragment<wmma::matrix_a, 16, 16, 8, wmma::precision::tf32, wmma::row_major> af[2];
            wmma::fragment<wmma::matrix_b, 16, 16, 8, wmma::precision::tf32, wmma::row_major> bf[4];
            #pragma unroll
            for (int i = 0; i < 2; ++i)
                wmma::load_matrix_sync(af[i], Ab + (wm * 32 + i * 16) * ALD + ks * 8, ALD);
            #pragma unroll
            for (int j = 0; j < 4; ++j)
                wmma::load_matrix_sync(bf[j], Bb + (ks * 8) * BLD + wn * 64 + j * 16, BLD);
            #pragma unroll
            for (int i = 0; i < 2; ++i)
                #pragma unroll
                for (int j = 0; j < 4; ++j)
                    wmma::mma_sync(cf[i][j], af[i], bf[j], cf[i][j]);
        }

        if (kt + 1 < kTiles) {
            float* An = As + ((kt + 1) & 1) * 128 * ALD;
            float* Bn = Bs + ((kt + 1) & 1) * 32 * BLD;
            #pragma unroll
            for (int i = 0; i < 4; ++i)
                *(float4*)(An + (arow_ + i * 32) * ALD + ac4) = tf32x4(ra[i]);
            #pragma unroll
            for (int i = 0; i < 4; ++i)
                *(float4*)(Bn + (brow_ + i * 8) * BLD + bc4) = tf32x4(rb[i]);
            __syncthreads();
        }
    }

    __syncthreads();
    float* Cs = sm;  // reuse smem: 128 x 128
    #pragma unroll
    for (int i = 0; i < 2; ++i)
        #pragma unroll
        for (int j = 0; j < 4; ++j)
            wmma::store_matrix_sync(Cs + (wm * 32 + i * 16) * 128 + wn * 64 + j * 16,
                                    cf[i][j], 128, wmma::mem_row_major);
    __syncthreads();

    #pragma unroll
    for (int it = 0; it < 16; ++it) {
        int f4 = tid + it * 256;        // 4096 float4 in tile
        int r = f4 >> 5, c4 = f4 & 31;
        float4 v = ((float4*)Cs)[f4];
        int gn = bn * 128 + c4 * 4;
        float4 bv = *(const float4*)(bias + gn);
        v.x += bv.x; v.y += bv.y; v.z += bv.z; v.w += bv.w;
        size_t goff = (size_t)(bm * 128 + r) * N + gn;
        if (EPI == EPI_BIAS_RES) {
            float4 rv = *(const float4*)(res + goff);
            v.x += rv.x; v.y += rv.y; v.z += rv.z; v.w += rv.w;
        }
        if (EPI == EPI_BIAS_GELU) {
            v.x = gelu_f(v.x); v.y = gelu_f(v.y);
            v.z = gelu_f(v.z); v.w = gelu_f(v.w);
        }
        *(float4*)(C + goff) = v;
    }
}

// ================= causal flash attention, tf32 WMMA =======================
// c layout: [SEQ, 3*DMODEL] rows = [q | k | v], head h at cols h*128.
// Block: (qt, h), 256 threads (8 warps). BQ=BK=64.
// S warp grid: 4(M) x 2(N): each warp 16x32 of S.
// O warp grid: 4(M) x 2(N): each warp 16x64 of O (HDIM=128).
#define QLD 132
#define SLD 68
#define ATT_FLOATS (3 * 64 * QLD + 64 * SLD + 256 + 3 * 64)
#define ATT_SMEM   (ATT_FLOATS * 4)

__global__ void __launch_bounds__(256)
attn_kernel(const float* __restrict__ c, float* __restrict__ out)
{
    const int h  = blockIdx.y;
    const int qt = gridDim.x - 1 - blockIdx.x;   // heavy tiles launched first

    extern __shared__ float smem[];
    float* Qs     = smem;                    // 64 x QLD
    float* Ks     = Qs + 64 * QLD;
    float* Vs     = Ks + 64 * QLD;
    float* S      = Vs + 64 * QLD;           // 64 x SLD
    float* rowpat = S + 64 * SLD;            // 16x16
    float* mrow   = rowpat + 256;            // 64
    float* lrow   = mrow + 64;               // 64
    float* arow   = lrow + 64;               // 64

    const int tid  = threadIdx.x;
    const int warp = tid >> 5;
    const int wm   = warp & 3;               // 16-row strip
    const int wn   = warp >> 2;              // 0/1

    // load Q tile (tf32 converted)
    #pragma unroll
    for (int i = 0; i < 8; ++i) {
        int idx = tid + i * 256;              // 2048 float4
        int r = idx >> 5, c4 = idx & 31;
        float4 v = *(const float4*)(c + (size_t)(qt * 64 + r) * (3 * DMODEL) + h * HDIM + c4 * 4);
        *(float4*)(Qs + r * QLD + c4 * 4) = tf32x4(v);
    }
    rowpat[tid] = (float)(tid >> 4);
    if (tid < 64) { mrow[tid] = -1e30f; lrow[tid] = 0.0f; }
    __syncthreads();

    // discover accumulator-fragment row mapping once
    wmma::fragment<wmma::accumulator, 16, 16, 8, float> rowf;
    wmma::load_matrix_sync(rowf, rowpat, 16, wmma::mem_row_major);
    int rowid[8];
    #pragma unroll
    for (int e = 0; e < 8; ++e) rowid[e] = (int)rowf.x[e];

    wmma::fragment<wmma::accumulator, 16, 16, 8, float> of[4];
    #pragma unroll
    for (int j = 0; j < 4; ++j) wmma::fill_fragment(of[j], 0.0f);

    const float scale = 0.022097086912079608f;  // 1/sqrt(2048)

    for (int j = 0; j <= qt; ++j) {
        __syncthreads();
        // load K, V tiles (tf32 converted)
        #pragma unroll
        for (int i = 0; i < 8; ++i) {
            int idx = tid + i * 256;
            int r = idx >> 5, c4 = idx & 31;
            size_t base = (size_t)(j * 64 + r) * (3 * DMODEL) + h * HDIM + c4 * 4;
            *(float4*)(Ks + r * QLD + c4 * 4) = tf32x4(*(const float4*)(c + base + DMODEL));
            *(float4*)(Vs + r * QLD + c4 * 4) = tf32x4(*(const float4*)(c + base + 2 * DMODEL));
        }
        __syncthreads();

        // S = Q @ K^T : each warp 16x32
        {
            wmma::fragment<wmma::accumulator, 16, 16, 8, float> sf[2];
            wmma::fill_fragment(sf[0], 0.0f);
            wmma::fill_fragment(sf[1], 0.0f);
            #pragma unroll
            for (int ks = 0; ks < 16; ++ks) {
                wmma::fragment<wmma::matrix_a, 16, 16, 8, wmma::precision::tf32, wmma::row_major> af;
                wmma::load_matrix_sync(af, Qs + (wm * 16) * QLD + ks * 8, QLD);
                #pragma unroll
                for (int jj = 0; jj < 2; ++jj) {
                    wmma::fragment<wmma::matrix_b, 16, 16, 8, wmma::precision::tf32, wmma::col_major> bf;
                    wmma::load_matrix_sync(bf, Ks + (wn * 32 + jj * 16) * QLD + ks * 8, QLD);
                    wmma::mma_sync(sf[jj], af, bf, sf[jj]);
                }
            }
            #pragma unroll
            for (int jj = 0; jj < 2; ++jj)
                wmma::store_matrix_sync(S + (wm * 16) * SLD + wn * 32 + jj * 16,
                                        sf[jj], SLD, wmma::mem_row_major);
        }
        __syncthreads();

        // online softmax per row (threads 0..63); store tf32(p)
        if (tid < 64) {
            const bool diag = (j == qt);
            float m_old = mrow[tid];
            float mx = m_old;
            float sv[64];
            #pragma unroll 8
            for (int k = 0; k < 64; ++k) {
                float v = S[tid * SLD + k] * scale;
                if (diag && k > tid) v = -1e30f;
                sv[k] = v;
                mx = fmaxf(mx, v);
            }
            float alpha = __expf(m_old - mx);
            float sum = 0.0f;
            #pragma unroll 8
            for (int k = 0; k < 64; ++k) {
                float p = __expf(sv[k] - mx);
                sum += p;
                S[tid * SLD + k] = wmma::__float_to_tf32(p);
            }
            mrow[tid] = mx;
            lrow[tid] = lrow[tid] * alpha + sum;
            arow[tid] = alpha;
        }
        __syncthreads();

        // rescale O accumulators, then O += P @ V (each warp 16x64)
        #pragma unroll
        for (int f = 0; f < 4; ++f)
            #pragma unroll
            for (int e = 0; e < 8; ++e)
                of[f].x[e] *= arow[wm * 16 + rowid[e]];

        #pragma unroll
        for (int ks = 0; ks < 8; ++ks) {
            wmma::fragment<wmma::matrix_a, 16, 16, 8, wmma::precision::tf32, wmma::row_major> pa;
            wmma::load_matrix_sync(pa, S + (wm * 16) * SLD + ks * 8, SLD);
            #pragma unroll
            for (int jj = 0; jj < 4; ++jj) {
                wmma::fragment<wmma::matrix_b, 16, 16, 8, wmma::precision::tf32, wmma::row_major> vb;
                wmma::load_matrix_sync(vb, Vs + (ks * 8) * QLD + wn * 64 + jj * 16, QLD);
                wmma::mma_sync(of[jj], pa, vb, of[jj]);
            }
        }
    }

    // write O (stage through Qs, then scale by 1/l)
    __syncthreads();
    #pragma unroll
    for (int jj = 0; jj < 4; ++jj)
        wmma::store_matrix_sync(Qs + (wm * 16) * QLD + wn * 64 + jj * 16,
                                of[jj], QLD, wmma::mem_row_major);
    __syncthreads();
    #pragma unroll
    for (int i = 0; i < 8; ++i) {
        int idx = tid + i * 256;
        int r = idx >> 5, c4 = idx & 31;
        float linv = 1.0f / lrow[r];
        float4 v = *(float4*)(Qs + r * QLD + c4 * 4);
        v.x *= linv; v.y *= linv; v.z *= linv; v.w *= linv;
        *(float4*)(out + (size_t)(qt * 64 + r) * DMODEL + h * HDIM + c4 * 4) = v;
    }
}

// ================= LayerNorm: one block per row =============================
__global__ void __launch_bounds__(256)
ln_kernel(const float* __restrict__ in, const float* __restrict__ g,
          const float* __restrict__ b, float* __restrict__ out)
{
    const int row = blockIdx.x;
    const int tid = threadIdx.x;
    const float4* x4 = (const float4*)(in + (size_t)row * DMODEL);

    float4 v0 = x4[tid];
    float4 v1 = x4[tid + 256];
    float s = v0.x + v0.y + v0.z + v0.w + v1.x + v1.y + v1.z + v1.w;
    float q = v0.x * v0.x + v0.y * v0.y + v0.z * v0.z + v0.w * v0.w
            + v1.x * v1.x + v1.y * v1.y + v1.z * v1.z + v1.w * v1.w;

    #pragma unroll
    for (int o = 16; o > 0; o >>= 1) {
        s += __shfl_down_sync(0xffffffffu, s, o);
        q += __shfl_down_sync(0xffffffffu, q, o);
    }
    __shared__ float rs[8], rq[8], fin[2];
    if ((tid & 31) == 0) { rs[tid >> 5] = s; rq[tid >> 5] = q; }
    __syncthreads();
    if (tid == 0) {
        float S = 0.0f, Q = 0.0f;
        #pragma unroll
        for (int i = 0; i < 8; ++i) { S += rs[i]; Q += rq[i]; }
        float mu  = S * (1.0f / DMODEL);
        float var = Q * (1.0f / DMODEL) - mu * mu;
        fin[0] = mu;
        fin[1] = rsqrtf(var + LN_EPS);
    }
    __syncthreads();
    float mu = fin[0], r = fin[1];

    float4 g0 = ((const float4*)g)[tid], g1 = ((const float4*)g)[tid + 256];
    float4 b0 = ((const float4*)b)[tid], b1 = ((const float4*)b)[tid + 256];
    float4 o0, o1;
    o0.x = (v0.x - mu) * r * g0.x + b0.x;
    o0.y = (v0.y - mu) * r * g0.y + b0.y;
    o0.z = (v0.z - mu) * r * g0.z + b0.z;
    o0.w = (v0.w - mu) * r * g0.w + b0.w;
    o1.x = (v1.x - mu) * r * g1.x + b1.x;
    o1.y = (v1.y - mu) * r * g1.y + b1.y;
    o1.z = (v1.z - mu) * r * g1.z + b1.z;
    o1.w = (v1.w - mu) * r * g1.w + b1.w;
    ((float4*)(out + (size_t)row * DMODEL))[tid]       = o0;
    ((float4*)(out + (size_t)row * DMODEL))[tid + 256] = o1;
}

// ================= launch ===================================================
extern "C" void kernel_launch(void* const* d_in, const int* in_sizes, int n_in,
                              void* d_out, int out_size)
{
    (void)in_sizes; (void)n_in; (void)out_size;

    const float* x     = (const float*)d_in[0];
    const float* C_w   = (const float*)d_in[1];
    const float* C_b   = (const float*)d_in[2];
    const float* lin_w = (const float*)d_in[3];
    const float* lin_b = (const float*)d_in[4];
    const float* ff1_w = (const float*)d_in[5];
    const float* ff1_b = (const float*)d_in[6];
    const float* ff2_w = (const float*)d_in[7];
    const float* ff2_b = (const float*)d_in[8];
    const float* ln1_g = (const float*)d_in[9];
    const float* ln1_b = (const float*)d_in[10];
    const float* ln2_g = (const float*)d_in[11];
    const float* ln2_b = (const float*)d_in[12];
    float* out = (float*)d_out;

    float *c, *attn, *res1, *h1, *ff, *res2;
    cudaGetSymbolAddress((void**)&c,    g_c);
    cudaGetSymbolAddress((void**)&attn, g_attn);
    cudaGetSymbolAddress((void**)&res1, g_res1);
    cudaGetSymbolAddress((void**)&h1,   g_h1);
    cudaGetSymbolAddress((void**)&ff,   g_ff);
    cudaGetSymbolAddress((void**)&res2, g_res2);

    const size_t gsm = (2 * 128 * ALD + 2 * 32 * BLD) * sizeof(float);  // ~69KB
    cudaFuncSetAttribute(gemm_tf32<EPI_BIAS>,      cudaFuncAttributeMaxDynamicSharedMemorySize, gsm);
    cudaFuncSetAttribute(gemm_tf32<EPI_BIAS_RES>,  cudaFuncAttributeMaxDynamicSharedMemorySize, gsm);
    cudaFuncSetAttribute(gemm_tf32<EPI_BIAS_GELU>, cudaFuncAttributeMaxDynamicSharedMemorySize, gsm);
    cudaFuncSetAttribute(attn_kernel,              cudaFuncAttributeMaxDynamicSharedMemorySize, ATT_SMEM);

    dim3 blk(256);

    // 1) QKV: c = x @ C_w + C_b          [2048, 6144]
    gemm_tf32<EPI_BIAS><<<dim3(3 * DMODEL / 128, SEQ / 128), blk, gsm>>>(
        x, C_w, C_b, nullptr, c, SEQ, 3 * DMODEL, DMODEL);

    // 2) causal attention -> attn        [2048, 2048]
    attn_kernel<<<dim3(SEQ / 64, HEADS), 256, ATT_SMEM>>>(c, attn);

    // 3) res1 = x + attn @ lin_w + lin_b
    gemm_tf32<EPI_BIAS_RES><<<dim3(DMODEL / 128, SEQ / 128), blk, gsm>>>(
        attn, lin_w, lin_b, x, res1, SEQ, DMODEL, DMODEL);

    // 4) h1 = LN1(res1)
    ln_kernel<<<SEQ, 256>>>(res1, ln1_g, ln1_b, h1);

    // 5) ff = gelu(h1 @ ff1_w + ff1_b)   [2048, 8192]
    gemm_tf32<EPI_BIAS_GELU><<<dim3(INNER / 128, SEQ / 128), blk, gsm>>>(
        h1, ff1_w, ff1_b, nullptr, ff, SEQ, INNER, DMODEL);

    // 6) res2 = h1 + ff @ ff2_w + ff2_b
    gemm_tf32<EPI_BIAS_RES><<<dim3(DMODEL / 128, SEQ / 128), blk, gsm>>>(
        ff, ff2_w, ff2_b, h1, res2, SEQ, DMODEL, INNER);

    // 7) out = LN2(res2)
    ln_kernel<<<SEQ, 256>>>(res2, ln2_g, ln2_b, out);
}

// round 5
// speedup vs baseline: 2.6288x; 1.2307x over previous
#include <cuda_runtime.h>
#include <cuda_bf16.h>
#include <cstdint>
#include <mma.h>
#include <math.h>

using namespace nvcuda;

// ---------------- constants ----------------
#define SEQ      2048
#define DMODEL   2048
#define HEADS    16
#define HDIM     128
#define INNER    8192
#define LN_EPS   1e-5f

// ---------------- scratch (static device memory; no allocations) ----------
__device__ float g_c[SEQ * 3 * DMODEL];     // QKV (tf32-rounded)
__device__ float g_attn[SEQ * DMODEL];      // attention out (tf32-rounded)
__device__ float g_res1[SEQ * DMODEL];      // x + proj(attn)   (full fp32)
__device__ float g_h1[SEQ * DMODEL];        // LN1 out (full fp32, residual)
__device__ float g_h1r[SEQ * DMODEL];       // LN1 out (tf32-rounded, GEMM A)
__device__ float g_ff[SEQ * INNER];         // gelu(...) (tf32-rounded)
__device__ float g_res2[SEQ * DMODEL];      // h1 + ff2 out (full fp32)
__device__ float g_xr[SEQ * DMODEL];        // x rounded (GEMM A)
// rounded weights (tf32-RN), original [K, N] layout
__device__ float g_Cwr[DMODEL * 3 * DMODEL];
__device__ float g_linr[DMODEL * DMODEL];
__device__ float g_ff1r[DMODEL * INNER];
__device__ float g_ff2r[INNER * DMODEL];

// ---------------- helpers ----------------
__device__ __forceinline__ float gelu_f(float v) {
    return 0.5f * v * (1.0f + erff(v * 0.7071067811865476f));
}
__device__ __forceinline__ float4 tf32x4(float4 v) {
    v.x = wmma::__float_to_tf32(v.x);
    v.y = wmma::__float_to_tf32(v.y);
    v.z = wmma::__float_to_tf32(v.z);
    v.w = wmma::__float_to_tf32(v.w);
    return v;
}
__device__ __forceinline__ uint32_t smem_u32(const void* p) {
    uint32_t a;
    asm("{ .reg .u64 t; cvta.to.shared.u64 t, %1; cvt.u32.u64 %0, t; }"
        : "=r"(a) : "l"(p));
    return a;
}
__device__ __forceinline__ void cp16(uint32_t dst, const void* src) {
    asm volatile("cp.async.cg.shared.global [%0], [%1], 16;" :: "r"(dst), "l"(src));
}
#define CP_COMMIT() asm volatile("cp.async.commit_group;" ::: "memory")
#define CP_WAIT(n)  asm volatile("cp.async.wait_group %0;" :: "n"(n) : "memory")

// ================= elementwise tf32-RN rounding =============================
__global__ void __launch_bounds__(256)
round_kernel(const float* __restrict__ in, float* __restrict__ out, int n4)
{
    int i = blockIdx.x * 256 + threadIdx.x;
    int stride = gridDim.x * 256;
    for (; i < n4; i += stride)
        ((float4*)out)[i] = tf32x4(((const float4*)in)[i]);
}

// ================= TF32 WMMA GEMM, 128x128x32 tiles, cp.async 3-stage =======
// C[M,N] = A[M,K] @ B[K,N] + bias (+res / gelu) (+round)
// A,B pre-rounded to tf32. 256 threads, warp grid 4(M) x 2(N), warp tile 32x64.
#define ALD 36
#define BLD 132
#define GSTAGES 3
#define STAGE_FLOATS (128 * ALD + 32 * BLD)     // 8832
#define GEMM_SMEM (GSTAGES * STAGE_FLOATS * 4)  // ~106KB

enum { EPI_BIAS = 0, EPI_BIAS_RES = 1, EPI_BIAS_GELU = 2 };

template <int EPI, bool ROUND>
__global__ void __launch_bounds__(256, 2)
gemm_tf32(const float* __restrict__ A, const float* __restrict__ B,
          const float* __restrict__ bias, const float* __restrict__ res,
          float* __restrict__ C, int M, int N, int K)
{
    extern __shared__ float sm[];
    const uint32_t sbase = smem_u32(sm);

    const int tid  = threadIdx.x;
    const int bm   = blockIdx.y;
    const int bn   = blockIdx.x;
    const int warp = tid >> 5;
    const int wm   = warp & 3;
    const int wn   = warp >> 2;

    wmma::fragment<wmma::accumulator, 16, 16, 8, float> cf[2][4];
    #pragma unroll
    for (int i = 0; i < 2; ++i)
        #pragma unroll
        for (int j = 0; j < 4; ++j)
            wmma::fill_fragment(cf[i][j], 0.0f);

    const float* Aptr = A + (size_t)(bm * 128) * K;
    const float* Bptr = B + (size_t)bn * 128;
    const int nT = K >> 5;

    // cp.async stage loader: A 128x32 (pad ALD), B 32x128 (pad BLD)
    const int ar = tid >> 3, ac = tid & 7;    // A: 8 chunks/row
    const int br = tid >> 5, bc = tid & 31;   // B: 32 chunks/row
    auto load_stage = [&](int s, int kt) {
        uint32_t as = sbase + (s * STAGE_FLOATS) * 4;
        uint32_t bs = as + 128 * ALD * 4;
        #pragma unroll
        for (int i = 0; i < 4; ++i) {
            int r = ar + i * 32;
            cp16(as + (r * ALD + ac * 4) * 4, Aptr + (size_t)r * K + kt * 32 + ac * 4);
        }
        #pragma unroll
        for (int i = 0; i < 4; ++i) {
            int r = br + i * 8;
            cp16(bs + (r * BLD + bc * 4) * 4, Bptr + (size_t)(kt * 32 + r) * N + bc * 4);
        }
    };

    load_stage(0, 0); CP_COMMIT();
    load_stage(1, 1); CP_COMMIT();

    for (int kt = 0; kt < nT; ++kt) {
        const int s = kt % GSTAGES;
        if (kt + 2 < nT) { load_stage((kt + 2) % GSTAGES, kt + 2); CP_COMMIT(); CP_WAIT(2); }
        else if (kt + 1 < nT) { CP_WAIT(1); }
        else { CP_WAIT(0); }
        __syncthreads();

        const float* As = sm + s * STAGE_FLOATS;
        const float* Bs = As + 128 * ALD;
        #pragma unroll
        for (int ks = 0; ks < 4; ++ks) {
            wmma::fragment<wmma::matrix_a, 16, 16, 8, wmma::precision::tf32, wmma::row_major> af[2];
            wmma::fragment<wmma::matrix_b, 16, 16, 8, wmma::precision::tf32, wmma::row_major> bf[4];
            #pragma unroll
            for (int i = 0; i < 2; ++i)
                wmma::load_matrix_sync(af[i], As + (wm * 32 + i * 16) * ALD + ks * 8, ALD);
            #pragma unroll
            for (int j = 0; j < 4; ++j)
                wmma::load_matrix_sync(bf[j], Bs + (ks * 8) * BLD + wn * 64 + j * 16, BLD);
            #pragma unroll
            for (int i = 0; i < 2; ++i)
                #pragma unroll
                for (int j = 0; j < 4; ++j)
                    wmma::mma_sync(cf[i][j], af[i], bf[j], cf[i][j]);
        }
        __syncthreads();
    }

    float* Cs = sm;  // 128x128 staging
    #pragma unroll
    for (int i = 0; i < 2; ++i)
        #pragma unroll
        for (int j = 0; j < 4; ++j)
            wmma::store_matrix_sync(Cs + (wm * 32 + i * 16) * 128 + wn * 64 + j * 16,
                                    cf[i][j], 128, wmma::mem_row_major);
    __syncthreads();

    #pragma unroll
    for (int it = 0; it < 16; ++it) {
        int f4 = tid + it * 256;
        int r = f4 >> 5, c4 = f4 & 31;
        float4 v = ((float4*)Cs)[f4];
        int gn = bn * 128 + c4 * 4;
        float4 bv = *(const float4*)(bias + gn);
        v.x += bv.x; v.y += bv.y; v.z += bv.z; v.w += bv.w;
        size_t goff = (size_t)(bm * 128 + r) * N + gn;
        if (EPI == EPI_BIAS_RES) {
            float4 rv = *(const float4*)(res + goff);
            v.x += rv.x; v.y += rv.y; v.z += rv.z; v.w += rv.w;
        }
        if (EPI == EPI_BIAS_GELU) {
            v.x = gelu_f(v.x); v.y = gelu_f(v.y);
            v.z = gelu_f(v.z); v.w = gelu_f(v.w);
        }
        if (ROUND) v = tf32x4(v);
        *(float4*)(C + goff) = v;
    }
}

// ================= causal flash attention, tf32 WMMA, cp.async KV ==========
// c pre-rounded tf32. Block (qt, h), 256 thr, BQ=BK=64, KV double-buffered.
#define QLD 132
#define SLD 68
#define OFF_Q   0
#define OFF_K   (64 * QLD)                 // 2 buffers
#define OFF_V   (OFF_K + 2 * 64 * QLD)     // 2 buffers
#define OFF_S   (OFF_V + 2 * 64 * QLD)
#define OFF_RP  (OFF_S + 64 * SLD)
#define OFF_M   (OFF_RP + 256)
#define OFF_L   (OFF_M + 64)
#define OFF_A   (OFF_L + 64)
#define ATT_FLOATS (OFF_A + 64)
#define ATT_SMEM   (ATT_FLOATS * 4)

__global__ void __launch_bounds__(256)
attn_kernel(const float* __restrict__ c, float* __restrict__ out)
{
    const int h  = blockIdx.y;
    const int qt = gridDim.x - 1 - blockIdx.x;   // heavy tiles first

    extern __shared__ float smem[];
    const uint32_t sbase = smem_u32(smem);
    float* Qs   = smem + OFF_Q;
    float* S    = smem + OFF_S;
    float* rowpat = smem + OFF_RP;
    float* mrow = smem + OFF_M;
    float* lrow = smem + OFF_L;
    float* arow = smem + OFF_A;

    const int tid  = threadIdx.x;
    const int warp = tid >> 5;
    const int wm   = warp & 3;
    const int wn   = warp >> 2;

    // cp.async mapping for 64x128 tiles (2048 chunks, 8/thread)
    const int kr = tid >> 5, kc = tid & 31;

    auto load_kv = [&](int buf, int j) {
        uint32_t kb = sbase + (OFF_K + buf * 64 * QLD) * 4;
        uint32_t vb = sbase + (OFF_V + buf * 64 * QLD) * 4;
        const float* base = c + (size_t)(j * 64) * (3 * DMODEL) + h * HDIM;
        #pragma unroll
        for (int i = 0; i < 8; ++i) {
            int r = kr + i * 8;
            const float* rp = base + (size_t)r * (3 * DMODEL) + kc * 4;
            cp16(kb + (r * QLD + kc * 4) * 4, rp + DMODEL);
            cp16(vb + (r * QLD + kc * 4) * 4, rp + 2 * DMODEL);
        }
    };

    // prologue: start KV(0), then load Q
    load_kv(0, 0); CP_COMMIT();

    #pragma unroll
    for (int i = 0; i < 8; ++i) {
        int idx = tid + i * 256;
        int r = idx >> 5, c4 = idx & 31;
        *(float4*)(Qs + r * QLD + c4 * 4) =
            *(const float4*)(c + (size_t)(qt * 64 + r) * (3 * DMODEL) + h * HDIM + c4 * 4);
    }
    rowpat[tid] = (float)(tid >> 4);
    if (tid < 64) { mrow[tid] = -1e30f; lrow[tid] = 0.0f; }
    __syncthreads();

    wmma::fragment<wmma::accumulator, 16, 16, 8, float> rowf;
    wmma::load_matrix_sync(rowf, rowpat, 16, wmma::mem_row_major);
    int rowid[8];
    #pragma unroll
    for (int e = 0; e < 8; ++e) rowid[e] = (int)rowf.x[e];

    wmma::fragment<wmma::accumulator, 16, 16, 8, float> of[4];
    #pragma unroll
    for (int j = 0; j < 4; ++j) wmma::fill_fragment(of[j], 0.0f);

    const float scale = 0.022097086912079608f;  // 1/sqrt(2048)
    const int srow = tid >> 2, sq = tid & 3;

    for (int j = 0; j <= qt; ++j) {
        if (j < qt) { load_kv((j + 1) & 1, j + 1); CP_COMMIT(); CP_WAIT(1); }
        else        { CP_WAIT(0); }
        __syncthreads();

        const float* Ks = smem + OFF_K + (j & 1) * 64 * QLD;
        const float* Vs = smem + OFF_V + (j & 1) * 64 * QLD;

        // S = Q @ K^T : each warp 16x32
        {
            wmma::fragment<wmma::accumulator, 16, 16, 8, float> sf[2];
            wmma::fill_fragment(sf[0], 0.0f);
            wmma::fill_fragment(sf[1], 0.0f);
            #pragma unroll
            for (int ks = 0; ks < 16; ++ks) {
                wmma::fragment<wmma::matrix_a, 16, 16, 8, wmma::precision::tf32, wmma::row_major> af;
                wmma::load_matrix_sync(af, Qs + (wm * 16) * QLD + ks * 8, QLD);
                #pragma unroll
                for (int jj = 0; jj < 2; ++jj) {
                    wmma::fragment<wmma::matrix_b, 16, 16, 8, wmma::precision::tf32, wmma::col_major> bf;
                    wmma::load_matrix_sync(bf, Ks + (wn * 32 + jj * 16) * QLD + ks * 8, QLD);
                    wmma::mma_sync(sf[jj], af, bf, sf[jj]);
                }
            }
            #pragma unroll
            for (int jj = 0; jj < 2; ++jj)
                wmma::store_matrix_sync(S + (wm * 16) * SLD + wn * 32 + jj * 16,
                                        sf[jj], SLD, wmma::mem_row_major);
        }
        __syncthreads();

        // online softmax: 4 threads per row (quad shuffles)
        {
            const bool diag = (j == qt);
            float m_old = mrow[srow];
            float mx = m_old;
            float sv[16];
            #pragma unroll
            for (int k = 0; k < 16; ++k) {
                int kcol = sq * 16 + k;
                float v = S[srow * SLD + kcol] * scale;
                if (diag && kcol > srow) v = -1e30f;
                sv[k] = v;
                mx = fmaxf(mx, v);
            }
            mx = fmaxf(mx, __shfl_xor_sync(0xffffffffu, mx, 1));
            mx = fmaxf(mx, __shfl_xor_sync(0xffffffffu, mx, 2));
            float sum = 0.0f;
            #pragma unroll
            for (int k = 0; k < 16; ++k) {
                float p = __expf(sv[k] - mx);
                sum += p;
                S[srow * SLD + sq * 16 + k] = wmma::__float_to_tf32(p);
            }
            sum += __shfl_xor_sync(0xffffffffu, sum, 1);
            sum += __shfl_xor_sync(0xffffffffu, sum, 2);
            if (sq == 0) {
                float alpha = __expf(m_old - mx);
                mrow[srow] = mx;
                lrow[srow] = lrow[srow] * alpha + sum;
                arow[srow] = alpha;
            }
        }
        __syncthreads();

        // rescale O, then O += P @ V (each warp 16x64)
        #pragma unroll
        for (int f = 0; f < 4; ++f)
            #pragma unroll
            for (int e = 0; e < 8; ++e)
                of[f].x[e] *= arow[wm * 16 + rowid[e]];

        #pragma unroll
        for (int ks = 0; ks < 8; ++ks) {
            wmma::fragment<wmma::matrix_a, 16, 16, 8, wmma::precision::tf32, wmma::row_major> pa;
            wmma::load_matrix_sync(pa, S + (wm * 16) * SLD + ks * 8, SLD);
            #pragma unroll
            for (int jj = 0; jj < 4; ++jj) {
                wmma::fragment<wmma::matrix_b, 16, 16, 8, wmma::precision::tf32, wmma::row_major> vb;
                wmma::load_matrix_sync(vb, Vs + (ks * 8) * QLD + wn * 64 + jj * 16, QLD);
                wmma::mma_sync(of[jj], pa, vb, of[jj]);
            }
        }
        __syncthreads();   // protect KV buffer before next iter's cp.async
    }

    // write O staged through Qs, scale 1/l, round tf32 (feeds proj GEMM)
    #pragma unroll
    for (int jj = 0; jj < 4; ++jj)
        wmma::store_matrix_sync(Qs + (wm * 16) * QLD + wn * 64 + jj * 16,
                                of[jj], QLD, wmma::mem_row_major);
    __syncthreads();
    #pragma unroll
    for (int i = 0; i < 8; ++i) {
        int idx = tid + i * 256;
        int r = idx >> 5, c4 = idx & 31;
        float linv = 1.0f / lrow[r];
        float4 v = *(float4*)(Qs + r * QLD + c4 * 4);
        v.x *= linv; v.y *= linv; v.z *= linv; v.w *= linv;
        *(float4*)(out + (size_t)(qt * 64 + r) * DMODEL + h * HDIM + c4 * 4) = tf32x4(v);
    }
}

// ================= LayerNorm: one block per row, optional rounded copy ======
__global__ void __launch_bounds__(256)
ln_kernel(const float* __restrict__ in, const float* __restrict__ g,
          const float* __restrict__ b, float* __restrict__ out,
          float* __restrict__ out_r)
{
    const int row = blockIdx.x;
    const int tid = threadIdx.x;
    const float4* x4 = (const float4*)(in + (size_t)row * DMODEL);

    float4 v0 = x4[tid];
    float4 v1 = x4[tid + 256];
    float s = v0.x + v0.y + v0.z + v0.w + v1.x + v1.y + v1.z + v1.w;
    float q = v0.x * v0.x + v0.y * v0.y + v0.z * v0.z + v0.w * v0.w
            + v1.x * v1.x + v1.y * v1.y + v1.z * v1.z + v1.w * v1.w;

    #pragma unroll
    for (int o = 16; o > 0; o >>= 1) {
        s += __shfl_down_sync(0xffffffffu, s, o);
        q += __shfl_down_sync(0xffffffffu, q, o);
    }
    __shared__ float rs[8], rq[8], fin[2];
    if ((tid & 31) == 0) { rs[tid >> 5] = s; rq[tid >> 5] = q; }
    __syncthreads();
    if (tid == 0) {
        float S = 0.0f, Q = 0.0f;
        #pragma unroll
        for (int i = 0; i < 8; ++i) { S += rs[i]; Q += rq[i]; }
        float mu  = S * (1.0f / DMODEL);
        float var = Q * (1.0f / DMODEL) - mu * mu;
        fin[0] = mu;
        fin[1] = rsqrtf(var + LN_EPS);
    }
    __syncthreads();
    float mu = fin[0], r = fin[1];

    float4 g0 = ((const float4*)g)[tid], g1 = ((const float4*)g)[tid + 256];
    float4 b0 = ((const float4*)b)[tid], b1 = ((const float4*)b)[tid + 256];
    float4 o0, o1;
    o0.x = (v0.x - mu) * r * g0.x + b0.x;
    o0.y = (v0.y - mu) * r * g0.y + b0.y;
    o0.z = (v0.z - mu) * r * g0.z + b0.z;
    o0.w = (v0.w - mu) * r * g0.w + b0.w;
    o1.x = (v1.x - mu) * r * g1.x + b1.x;
    o1.y = (v1.y - mu) * r * g1.y + b1.y;
    o1.z = (v1.z - mu) * r * g1.z + b1.z;
    o1.w = (v1.w - mu) * r * g1.w + b1.w;
    ((float4*)(out + (size_t)row * DMODEL))[tid]       = o0;
    ((float4*)(out + (size_t)row * DMODEL))[tid + 256] = o1;
    if (out_r) {
        ((float4*)(out_r + (size_t)row * DMODEL))[tid]       = tf32x4(o0);
        ((float4*)(out_r + (size_t)row * DMODEL))[tid + 256] = tf32x4(o1);
    }
}

// ================= launch ===================================================
extern "C" void kernel_launch(void* const* d_in, const int* in_sizes, int n_in,
                              void* d_out, int out_size)
{
    (void)in_sizes; (void)n_in; (void)out_size;

    const float* x     = (const float*)d_in[0];
    const float* C_w   = (const float*)d_in[1];
    const float* C_b   = (const float*)d_in[2];
    const float* lin_w = (const float*)d_in[3];
    const float* lin_b = (const float*)d_in[4];
    const float* ff1_w = (const float*)d_in[5];
    const float* ff1_b = (const float*)d_in[6];
    const float* ff2_w = (const float*)d_in[7];
    const float* ff2_b = (const float*)d_in[8];
    const float* ln1_g = (const float*)d_in[9];
    const float* ln1_b = (const float*)d_in[10];
    const float* ln2_g = (const float*)d_in[11];
    const float* ln2_b = (const float*)d_in[12];
    float* out = (float*)d_out;

    float *c, *attn, *res1, *h1, *h1r, *ff, *res2, *xr;
    float *Cwr, *linr, *ff1r, *ff2r;
    cudaGetSymbolAddress((void**)&c,    g_c);
    cudaGetSymbolAddress((void**)&attn, g_attn);
    cudaGetSymbolAddress((void**)&res1, g_res1);
    cudaGetSymbolAddress((void**)&h1,   g_h1);
    cudaGetSymbolAddress((void**)&h1r,  g_h1r);
    cudaGetSymbolAddress((void**)&ff,   g_ff);
    cudaGetSymbolAddress((void**)&res2, g_res2);
    cudaGetSymbolAddress((void**)&xr,   g_xr);
    cudaGetSymbolAddress((void**)&Cwr,  g_Cwr);
    cudaGetSymbolAddress((void**)&linr, g_linr);
    cudaGetSymbolAddress((void**)&ff1r, g_ff1r);
    cudaGetSymbolAddress((void**)&ff2r, g_ff2r);

    cudaFuncSetAttribute((const void*)gemm_tf32<EPI_BIAS, true>,       cudaFuncAttributeMaxDynamicSharedMemorySize, GEMM_SMEM);
    cudaFuncSetAttribute((const void*)gemm_tf32<EPI_BIAS_RES, false>,  cudaFuncAttributeMaxDynamicSharedMemorySize, GEMM_SMEM);
    cudaFuncSetAttribute((const void*)gemm_tf32<EPI_BIAS_GELU, true>,  cudaFuncAttributeMaxDynamicSharedMemorySize, GEMM_SMEM);
    cudaFuncSetAttribute((const void*)attn_kernel,                     cudaFuncAttributeMaxDynamicSharedMemorySize, ATT_SMEM);

    // 0) tf32-RN round all GEMM inputs
    round_kernel<<<512, 256>>>(x,     xr,   SEQ * DMODEL / 4);
    round_kernel<<<512, 256>>>(C_w,   Cwr,  DMODEL * 3 * DMODEL / 4);
    round_kernel<<<512, 256>>>(lin_w, linr, DMODEL * DMODEL / 4);
    round_kernel<<<512, 256>>>(ff1_w, ff1r, DMODEL * INNER / 4);
    round_kernel<<<512, 256>>>(ff2_w, ff2r, INNER * DMODEL / 4);

    // 1) QKV: c = round(xr @ C_w + C_b)   [2048, 6144]
    gemm_tf32<EPI_BIAS, true><<<dim3(3 * DMODEL / 128, SEQ / 128), 256, GEMM_SMEM>>>(
        xr, Cwr, C_b, nullptr, c, SEQ, 3 * DMODEL, DMODEL);

    // 2) causal attention -> attn (rounded)
    attn_kernel<<<dim3(SEQ / 64, HEADS), 256, ATT_SMEM>>>(c, attn);

    // 3) res1 = x + attn @ lin_w + lin_b
    gemm_tf32<EPI_BIAS_RES, false><<<dim3(DMODEL / 128, SEQ / 128), 256, GEMM_SMEM>>>(
        attn, linr, lin_b, x, res1, SEQ, DMODEL, DMODEL);

    // 4) h1 = LN1(res1); h1r = round(h1)
    ln_kernel<<<SEQ, 256>>>(res1, ln1_g, ln1_b, h1, h1r);

    // 5) ff = round(gelu(h1r @ ff1_w + ff1_b))   [2048, 8192]
    gemm_tf32<EPI_BIAS_GELU, true><<<dim3(INNER / 128, SEQ / 128), 256, GEMM_SMEM>>>(
        h1r, ff1r, ff1_b, nullptr, ff, SEQ, INNER, DMODEL);

    // 6) res2 = h1 + ff @ ff2_w + ff2_b
    gemm_tf32<EPI_BIAS_RES, false><<<dim3(DMODEL / 128, SEQ / 128), 256, GEMM_SMEM>>>(
        ff, ff2r, ff2_b, h1, res2, SEQ, DMODEL, INNER);

    // 7) out = LN2(res2)
    ln_kernel<<<SEQ, 256>>>(res2, ln2_g, ln2_b, out, nullptr);
}

// round 6
// speedup vs baseline: 10.1675x; 3.8677x over previous
#include <cuda_runtime.h>
#include <cuda_fp16.h>
#include <cstdint>
#include <mma.h>
#include <math.h>

using namespace nvcuda;

// ---------------- constants ----------------
#define SEQ      2048
#define DMODEL   2048
#define HEADS    16
#define HDIM     128
#define INNER    8192
#define LN_EPS   1e-5f

// ---------------- scratch (static device memory; no allocations) ----------
__device__ __half g_c[SEQ * 3 * DMODEL];     // QKV (half)
__device__ __half g_attn[SEQ * DMODEL];      // attention out (half)
__device__ float  g_res1[SEQ * DMODEL];      // x + proj(attn)
__device__ float  g_h1[SEQ * DMODEL];        // LN1 out fp32 (residual)
__device__ __half g_h1h[SEQ * DMODEL];       // LN1 out half (GEMM A)
__device__ __half g_ff[SEQ * INNER];         // gelu(...) half
__device__ float  g_res2[SEQ * DMODEL];
__device__ __half g_xh[SEQ * DMODEL];        // x half
__device__ __half g_Cwh[DMODEL * 3 * DMODEL];
__device__ __half g_linh[DMODEL * DMODEL];
__device__ __half g_ff1h[DMODEL * INNER];
__device__ __half g_ff2h[INNER * DMODEL];

// ---------------- helpers ----------------
__device__ __forceinline__ float gelu_f(float v) {
    return 0.5f * v * (1.0f + erff(v * 0.7071067811865476f));
}
__device__ __forceinline__ uint32_t smem_u32(const void* p) {
    uint32_t a;
    asm("{ .reg .u64 t; cvta.to.shared.u64 t, %1; cvt.u32.u64 %0, t; }"
        : "=r"(a) : "l"(p));
    return a;
}
__device__ __forceinline__ void cp16(uint32_t dst, const void* src) {
    asm volatile("cp.async.cg.shared.global [%0], [%1], 16;" :: "r"(dst), "l"(src));
}
#define CP_COMMIT() asm volatile("cp.async.commit_group;" ::: "memory")
#define CP_WAIT(n)  asm volatile("cp.async.wait_group %0;" :: "n"(n) : "memory")

// ================= float -> half conversion =================================
__global__ void __launch_bounds__(256)
f2h_kernel(const float* __restrict__ in, __half* __restrict__ out, int n4)
{
    int i = blockIdx.x * 256 + threadIdx.x;
    int stride = gridDim.x * 256;
    for (; i < n4; i += stride) {
        float4 v = ((const float4*)in)[i];
        __half2 p0 = __floats2half2_rn(v.x, v.y);
        __half2 p1 = __floats2half2_rn(v.z, v.w);
        uint2 u;
        u.x = *(uint32_t*)&p0;
        u.y = *(uint32_t*)&p1;
        ((uint2*)out)[i] = u;
    }
}

// ================= FP16 WMMA GEMM, 128x128x64 tiles, cp.async 3-stage =======
// C[M,N] = A[M,K] @ B[K,N] + bias (+res / gelu). A,B half; accum fp32.
// 256 threads, warp grid 4(M) x 2(N), warp tile 32x64.
#define ALD 72     // halves; 144B/row
#define BLD 136    // halves; 272B/row
#define GSTAGES 3
#define STAGE_BYTES (128 * 144 + 64 * 272)      // 35840
#define GEMM_SMEM   (GSTAGES * STAGE_BYTES)     // 107520

enum { EPI_BIAS = 0, EPI_BIAS_RES = 1, EPI_BIAS_GELU = 2 };

template <int EPI, bool OUTH>
__global__ void __launch_bounds__(256, 2)
gemm_fp16(const __half* __restrict__ A, const __half* __restrict__ B,
          const float* __restrict__ bias, const float* __restrict__ res,
          void* __restrict__ Cout, int M, int N, int K)
{
    extern __shared__ char smg[];
    const uint32_t sbase = smem_u32(smg);

    const int tid  = threadIdx.x;
    const int bm   = blockIdx.y;
    const int bn   = blockIdx.x;
    const int warp = tid >> 5;
    const int wm   = warp & 3;
    const int wn   = warp >> 2;

    wmma::fragment<wmma::accumulator, 16, 16, 16, float> cf[2][4];
    #pragma unroll
    for (int i = 0; i < 2; ++i)
        #pragma unroll
        for (int j = 0; j < 4; ++j)
            wmma::fill_fragment(cf[i][j], 0.0f);

    const __half* Aptr = A + (size_t)(bm * 128) * K;
    const __half* Bptr = B + (size_t)bn * 128;
    const int nT = K >> 6;

    // A: 128 rows x 64 half (8 chunks/row). B: 64 rows x 128 half (16 chunks/row).
    auto load_stage = [&](int s, int kt) {
        uint32_t sa = sbase + s * STAGE_BYTES;
        uint32_t sb = sa + 128 * 144;
        #pragma unroll
        for (int i = 0; i < 4; ++i) {
            int idx = tid + i * 256;
            int r = idx >> 3, c = idx & 7;
            cp16(sa + r * 144 + c * 16, Aptr + (size_t)r * K + kt * 64 + c * 8);
        }
        #pragma unroll
        for (int i = 0; i < 4; ++i) {
            int idx = tid + i * 256;
            int r = idx >> 4, c = idx & 15;
            cp16(sb + r * 272 + c * 16, Bptr + (size_t)(kt * 64 + r) * N + c * 8);
        }
    };

    load_stage(0, 0); CP_COMMIT();
    load_stage(1, 1); CP_COMMIT();

    for (int kt = 0; kt < nT; ++kt) {
        const int s = kt % GSTAGES;
        if (kt + 2 < nT) { load_stage((kt + 2) % GSTAGES, kt + 2); CP_COMMIT(); CP_WAIT(2); }
        else if (kt + 1 < nT) { CP_WAIT(1); }
        else { CP_WAIT(0); }
        __syncthreads();

        const __half* As = (const __half*)(smg + s * STAGE_BYTES);
        const __half* Bs = As + 128 * ALD;
        #pragma unroll
        for (int ks = 0; ks < 4; ++ks) {
            wmma::fragment<wmma::matrix_a, 16, 16, 16, __half, wmma::row_major> af[2];
            wmma::fragment<wmma::matrix_b, 16, 16, 16, __half, wmma::row_major> bf[4];
            #pragma unroll
            for (int i = 0; i < 2; ++i)
                wmma::load_matrix_sync(af[i], As + (wm * 32 + i * 16) * ALD + ks * 16, ALD);
            #pragma unroll
            for (int j = 0; j < 4; ++j)
                wmma::load_matrix_sync(bf[j], Bs + (ks * 16) * BLD + wn * 64 + j * 16, BLD);
            #pragma unroll
            for (int i = 0; i < 2; ++i)
                #pragma unroll
                for (int j = 0; j < 4; ++j)
                    wmma::mma_sync(cf[i][j], af[i], bf[j], cf[i][j]);
        }
        __syncthreads();
    }

    float* Cs = (float*)smg;  // 128x128 fp32 staging (64KB)
    #pragma unroll
    for (int i = 0; i < 2; ++i)
        #pragma unroll
        for (int j = 0; j < 4; ++j)
            wmma::store_matrix_sync(Cs + (wm * 32 + i * 16) * 128 + wn * 64 + j * 16,
                                    cf[i][j], 128, wmma::mem_row_major);
    __syncthreads();

    #pragma unroll
    for (int it = 0; it < 16; ++it) {
        int f4 = tid + it * 256;
        int r = f4 >> 5, c4 = f4 & 31;
        float4 v = ((float4*)Cs)[f4];
        int gn = bn * 128 + c4 * 4;
        float4 bv = *(const float4*)(bias + gn);
        v.x += bv.x; v.y += bv.y; v.z += bv.z; v.w += bv.w;
        size_t goff = (size_t)(bm * 128 + r) * N + gn;
        if (EPI == EPI_BIAS_RES) {
            float4 rv = *(const float4*)(res + goff);
            v.x += rv.x; v.y += rv.y; v.z += rv.z; v.w += rv.w;
        }
        if (EPI == EPI_BIAS_GELU) {
            v.x = gelu_f(v.x); v.y = gelu_f(v.y);
            v.z = gelu_f(v.z); v.w = gelu_f(v.w);
        }
        if (OUTH) {
            __half2 p0 = __floats2half2_rn(v.x, v.y);
            __half2 p1 = __floats2half2_rn(v.z, v.w);
            uint2 u;
            u.x = *(uint32_t*)&p0;
            u.y = *(uint32_t*)&p1;
            *(uint2*)((__half*)Cout + goff) = u;
        } else {
            *(float4*)((float*)Cout + goff) = v;
        }
    }
}

// ================= causal flash attention, fp16 WMMA, cp.async KV ==========
// c half [SEQ, 3*DMODEL]. Block (qt, h), 256 thr, BQ=BK=64, KV double-buffered.
#define QLDH 136                              // halves (272B rows)
#define SLDF 68                               // fp32
#define PLDH 72                               // halves
#define OFF_Q   0                             // 64*272 = 17408 B
#define OFF_K   17408                         // 2 x 17408
#define OFF_V   (OFF_K + 2 * 17408)
#define OFF_S   (OFF_V + 2 * 17408)           // 64*68*4 = 17408 B
#define OFF_P   (OFF_S + 17408)               // 64*72*2 = 9216 B
#define OFF_RP  (OFF_P + 9216)                // 256*4
#define OFF_M   (OFF_RP + 1024)               // 64*4
#define OFF_L   (OFF_M + 256)
#define OFF_A   (OFF_L + 256)
#define ATT_SMEM (OFF_A + 256)

__global__ void __launch_bounds__(256)
attn_kernel(const __half* __restrict__ c, __half* __restrict__ out)
{
    const int h  = blockIdx.y;
    const int qt = gridDim.x - 1 - blockIdx.x;   // heavy tiles first

    extern __shared__ char smg[];
    const uint32_t sbase = smem_u32(smg);
    __half* Qs   = (__half*)(smg + OFF_Q);
    float*  S    = (float*)(smg + OFF_S);
    __half* P    = (__half*)(smg + OFF_P);
    float* rowpat = (float*)(smg + OFF_RP);
    float* mrow  = (float*)(smg + OFF_M);
    float* lrow  = (float*)(smg + OFF_L);
    float* arow  = (float*)(smg + OFF_A);

    const int tid  = threadIdx.x;
    const int warp = tid >> 5;
    const int wm   = warp & 3;
    const int wn   = warp >> 2;

    // KV tiles: 64 rows x 128 halves = 16 chunks/row, 1024 chunks, 4/thread each
    auto load_kv = [&](int buf, int j) {
        uint32_t kb = sbase + OFF_K + buf * 17408;
        uint32_t vb = sbase + OFF_V + buf * 17408;
        const __half* base = c + (size_t)(j * 64) * (3 * DMODEL) + h * HDIM;
        #pragma unroll
        for (int i = 0; i < 4; ++i) {
            int idx = tid + i * 256;
            int r = idx >> 4, cc = idx & 15;
            const __half* rp = base + (size_t)r * (3 * DMODEL) + cc * 8;
            cp16(kb + r * 272 + cc * 16, rp + DMODEL);
            cp16(vb + r * 272 + cc * 16, rp + 2 * DMODEL);
        }
    };

    load_kv(0, 0); CP_COMMIT();

    // Q load (regular ld, one-time)
    #pragma unroll
    for (int i = 0; i < 4; ++i) {
        int idx = tid + i * 256;
        int r = idx >> 4, cc = idx & 15;
        *(uint4*)((char*)Qs + r * 272 + cc * 16) =
            *(const uint4*)(c + (size_t)(qt * 64 + r) * (3 * DMODEL) + h * HDIM + cc * 8);
    }
    rowpat[tid] = (float)(tid >> 4);
    if (tid < 64) { mrow[tid] = -1e30f; lrow[tid] = 0.0f; }
    __syncthreads();

    wmma::fragment<wmma::accumulator, 16, 16, 16, float> rowf;
    wmma::load_matrix_sync(rowf, rowpat, 16, wmma::mem_row_major);
    int rowid[8];
    #pragma unroll
    for (int e = 0; e < 8; ++e) rowid[e] = (int)rowf.x[e];

    wmma::fragment<wmma::accumulator, 16, 16, 16, float> of[4];
    #pragma unroll
    for (int j = 0; j < 4; ++j) wmma::fill_fragment(of[j], 0.0f);

    const float scale = 0.022097086912079608f;  // 1/sqrt(2048)
    const int srow = tid >> 2, sq = tid & 3;

    for (int j = 0; j <= qt; ++j) {
        if (j < qt) { load_kv((j + 1) & 1, j + 1); CP_COMMIT(); CP_WAIT(1); }
        else        { CP_WAIT(0); }
        __syncthreads();

        const __half* Ks = (const __half*)(smg + OFF_K + (j & 1) * 17408);
        const __half* Vs = (const __half*)(smg + OFF_V + (j & 1) * 17408);

        // S = Q @ K^T : each warp 16x32, 8 k-steps of 16
        {
            wmma::fragment<wmma::accumulator, 16, 16, 16, float> sf[2];
            wmma::fill_fragment(sf[0], 0.0f);
            wmma::fill_fragment(sf[1], 0.0f);
            #pragma unroll
            for (int ks = 0; ks < 8; ++ks) {
                wmma::fragment<wmma::matrix_a, 16, 16, 16, __half, wmma::row_major> af;
                wmma::load_matrix_sync(af, Qs + (wm * 16) * QLDH + ks * 16, QLDH);
                #pragma unroll
                for (int jj = 0; jj < 2; ++jj) {
                    wmma::fragment<wmma::matrix_b, 16, 16, 16, __half, wmma::col_major> bf;
                    wmma::load_matrix_sync(bf, Ks + (wn * 32 + jj * 16) * QLDH + ks * 16, QLDH);
                    wmma::mma_sync(sf[jj], af, bf, sf[jj]);
                }
            }
            #pragma unroll
            for (int jj = 0; jj < 2; ++jj)
                wmma::store_matrix_sync(S + (wm * 16) * SLDF + wn * 32 + jj * 16,
                                        sf[jj], SLDF, wmma::mem_row_major);
        }
        __syncthreads();

        // online softmax: 4 threads/row, quad shuffles; P written as half
        {
            const bool diag = (j == qt);
            float m_old = mrow[srow];
            float mx = m_old;
            float sv[16];
            #pragma unroll
            for (int k = 0; k < 16; ++k) {
                int kcol = sq * 16 + k;
                float v = S[srow * SLDF + kcol] * scale;
                if (diag && kcol > srow) v = -1e30f;
                sv[k] = v;
                mx = fmaxf(mx, v);
            }
            mx = fmaxf(mx, __shfl_xor_sync(0xffffffffu, mx, 1));
            mx = fmaxf(mx, __shfl_xor_sync(0xffffffffu, mx, 2));
            float sum = 0.0f;
            #pragma unroll
            for (int k = 0; k < 16; ++k) {
                float p = __expf(sv[k] - mx);
                sum += p;
                P[srow * PLDH + sq * 16 + k] = __float2half_rn(p);
            }
            sum += __shfl_xor_sync(0xffffffffu, sum, 1);
            sum += __shfl_xor_sync(0xffffffffu, sum, 2);
            if (sq == 0) {
                float alpha = __expf(m_old - mx);
                mrow[srow] = mx;
                lrow[srow] = lrow[srow] * alpha + sum;
                arow[srow] = alpha;
            }
        }
        __syncthreads();

        // rescale O, then O += P @ V (each warp 16x64, 4 k-steps)
        #pragma unroll
        for (int f = 0; f < 4; ++f)
            #pragma unroll
            for (int e = 0; e < 8; ++e)
                of[f].x[e] *= arow[wm * 16 + rowid[e]];

        #pragma unroll
        for (int ks = 0; ks < 4; ++ks) {
            wmma::fragment<wmma::matrix_a, 16, 16, 16, __half, wmma::row_major> pa;
            wmma::load_matrix_sync(pa, P + (wm * 16) * PLDH + ks * 16, PLDH);
            #pragma unroll
            for (int jj = 0; jj < 4; ++jj) {
                wmma::fragment<wmma::matrix_b, 16, 16, 16, __half, wmma::row_major> vb;
                wmma::load_matrix_sync(vb, Vs + (ks * 16) * QLDH + wn * 64 + jj * 16, QLDH);
                wmma::mma_sync(of[jj], pa, vb, of[jj]);
            }
        }
        __syncthreads();   // protect KV buffers before next iter's cp.async
    }

    // O: stage fp32 in K-buffer region, scale 1/l, write half
    float* Os = (float*)(smg + OFF_K);   // 64 x 132 fp32 = 33792 B < 34816 B
    #pragma unroll
    for (int jj = 0; jj < 4; ++jj)
        wmma::store_matrix_sync(Os + (wm * 16) * 132 + wn * 64 + jj * 16,
                                of[jj], 132, wmma::mem_row_major);
    __syncthreads();
    #pragma unroll
    for (int i = 0; i < 8; ++i) {
        int idx = tid + i * 256;
        int r = idx >> 5, c4 = idx & 31;
        float linv = 1.0f / lrow[r];
        float4 v = *(float4*)(Os + r * 132 + c4 * 4);
        __half2 p0 = __floats2half2_rn(v.x * linv, v.y * linv);
        __half2 p1 = __floats2half2_rn(v.z * linv, v.w * linv);
        uint2 u;
        u.x = *(uint32_t*)&p0;
        u.y = *(uint32_t*)&p1;
        *(uint2*)(out + (size_t)(qt * 64 + r) * DMODEL + h * HDIM + c4 * 4) = u;
    }
}

// ================= LayerNorm: one block per row, optional half copy =========
__global__ void __launch_bounds__(256)
ln_kernel(const float* __restrict__ in, const float* __restrict__ g,
          const float* __restrict__ b, float* __restrict__ out,
          __half* __restrict__ out_h)
{
    const int row = blockIdx.x;
    const int tid = threadIdx.x;
    const float4* x4 = (const float4*)(in + (size_t)row * DMODEL);

    float4 v0 = x4[tid];
    float4 v1 = x4[tid + 256];
    float s = v0.x + v0.y + v0.z + v0.w + v1.x + v1.y + v1.z + v1.w;
    float q = v0.x * v0.x + v0.y * v0.y + v0.z * v0.z + v0.w * v0.w
            + v1.x * v1.x + v1.y * v1.y + v1.z * v1.z + v1.w * v1.w;

    #pragma unroll
    for (int o = 16; o > 0; o >>= 1) {
        s += __shfl_down_sync(0xffffffffu, s, o);
        q += __shfl_down_sync(0xffffffffu, q, o);
    }
    __shared__ float rs[8], rq[8], fin[2];
    if ((tid & 31) == 0) { rs[tid >> 5] = s; rq[tid >> 5] = q; }
    __syncthreads();
    if (tid == 0) {
        float S = 0.0f, Q = 0.0f;
        #pragma unroll
        for (int i = 0; i < 8; ++i) { S += rs[i]; Q += rq[i]; }
        float mu  = S * (1.0f / DMODEL);
        float var = Q * (1.0f / DMODEL) - mu * mu;
        fin[0] = mu;
        fin[1] = rsqrtf(var + LN_EPS);
    }
    __syncthreads();
    float mu = fin[0], r = fin[1];

    float4 g0 = ((const float4*)g)[tid], g1 = ((const float4*)g)[tid + 256];
    float4 b0 = ((const float4*)b)[tid], b1 = ((const float4*)b)[tid + 256];
    float4 o0, o1;
    o0.x = (v0.x - mu) * r * g0.x + b0.x;
    o0.y = (v0.y - mu) * r * g0.y + b0.y;
    o0.z = (v0.z - mu) * r * g0.z + b0.z;
    o0.w = (v0.w - mu) * r * g0.w + b0.w;
    o1.x = (v1.x - mu) * r * g1.x + b1.x;
    o1.y = (v1.y - mu) * r * g1.y + b1.y;
    o1.z = (v1.z - mu) * r * g1.z + b1.z;
    o1.w = (v1.w - mu) * r * g1.w + b1.w;
    ((float4*)(out + (size_t)row * DMODEL))[tid]       = o0;
    ((float4*)(out + (size_t)row * DMODEL))[tid + 256] = o1;
    if (out_h) {
        __half2 a0 = __floats2half2_rn(o0.x, o0.y);
        __half2 a1 = __floats2half2_rn(o0.z, o0.w);
        __half2 a2 = __floats2half2_rn(o1.x, o1.y);
        __half2 a3 = __floats2half2_rn(o1.z, o1.w);
        uint2 u0, u1;
        u0.x = *(uint32_t*)&a0; u0.y = *(uint32_t*)&a1;
        u1.x = *(uint32_t*)&a2; u1.y = *(uint32_t*)&a3;
        ((uint2*)(out_h + (size_t)row * DMODEL))[tid]       = u0;
        ((uint2*)(out_h + (size_t)row * DMODEL))[tid + 256] = u1;
    }
}

// ================= launch ===================================================
extern "C" void kernel_launch(void* const* d_in, const int* in_sizes, int n_in,
                              void* d_out, int out_size)
{
    (void)in_sizes; (void)n_in; (void)out_size;

    const float* x     = (const float*)d_in[0];
    const float* C_w   = (const float*)d_in[1];
    const float* C_b   = (const float*)d_in[2];
    const float* lin_w = (const float*)d_in[3];
    const float* lin_b = (const float*)d_in[4];
    const float* ff1_w = (const float*)d_in[5];
    const float* ff1_b = (const float*)d_in[6];
    const float* ff2_w = (const float*)d_in[7];
    const float* ff2_b = (const float*)d_in[8];
    const float* ln1_g = (const float*)d_in[9];
    const float* ln1_b = (const float*)d_in[10];
    const float* ln2_g = (const float*)d_in[11];
    const float* ln2_b = (const float*)d_in[12];
    float* out = (float*)d_out;

    __half *c, *attn, *h1h, *ff, *xh, *Cwh, *linh, *ff1h, *ff2h;
    float *res1, *h1, *res2;
    cudaGetSymbolAddress((void**)&c,    g_c);
    cudaGetSymbolAddress((void**)&attn, g_attn);
    cudaGetSymbolAddress((void**)&res1, g_res1);
    cudaGetSymbolAddress((void**)&h1,   g_h1);
    cudaGetSymbolAddress((void**)&h1h,  g_h1h);
    cudaGetSymbolAddress((void**)&ff,   g_ff);
    cudaGetSymbolAddress((void**)&res2, g_res2);
    cudaGetSymbolAddress((void**)&xh,   g_xh);
    cudaGetSymbolAddress((void**)&Cwh,  g_Cwh);
    cudaGetSymbolAddress((void**)&linh, g_linh);
    cudaGetSymbolAddress((void**)&ff1h, g_ff1h);
    cudaGetSymbolAddress((void**)&ff2h, g_ff2h);

    cudaFuncSetAttribute((const void*)gemm_fp16<EPI_BIAS, true>,       cudaFuncAttributeMaxDynamicSharedMemorySize, GEMM_SMEM);
    cudaFuncSetAttribute((const void*)gemm_fp16<EPI_BIAS_RES, false>,  cudaFuncAttributeMaxDynamicSharedMemorySize, GEMM_SMEM);
    cudaFuncSetAttribute((const void*)gemm_fp16<EPI_BIAS_GELU, true>,  cudaFuncAttributeMaxDynamicSharedMemorySize, GEMM_SMEM);
    cudaFuncSetAttribute((const void*)attn_kernel,                     cudaFuncAttributeMaxDynamicSharedMemorySize, ATT_SMEM);

    // 0) convert inputs to half
    f2h_kernel<<<512, 256>>>(x,     xh,   SEQ * DMODEL / 4);
    f2h_kernel<<<512, 256>>>(C_w,   Cwh,  DMODEL * 3 * DMODEL / 4);
    f2h_kernel<<<512, 256>>>(lin_w, linh, DMODEL * DMODEL / 4);
    f2h_kernel<<<512, 256>>>(ff1_w, ff1h, DMODEL * INNER / 4);
    f2h_kernel<<<512, 256>>>(ff2_w, ff2h, INNER * DMODEL / 4);

    // 1) QKV: c = half(xh @ C_w + C_b)   [2048, 6144]
    gemm_fp16<EPI_BIAS, true><<<dim3(3 * DMODEL / 128, SEQ / 128), 256, GEMM_SMEM>>>(
        xh, Cwh, C_b, nullptr, c, SEQ, 3 * DMODEL, DMODEL);

    // 2) causal attention -> attn (half)
    attn_kernel<<<dim3(SEQ / 64, HEADS), 256, ATT_SMEM>>>(c, attn);

    // 3) res1 = x + attn @ lin_w + lin_b  (fp32)
    gemm_fp16<EPI_BIAS_RES, false><<<dim3(DMODEL / 128, SEQ / 128), 256, GEMM_SMEM>>>(
        attn, linh, lin_b, x, res1, SEQ, DMODEL, DMODEL);

    // 4) h1 = LN1(res1); h1h = half(h1)
    ln_kernel<<<SEQ, 256>>>(res1, ln1_g, ln1_b, h1, h1h);

    // 5) ff = half(gelu(h1h @ ff1_w + ff1_b))   [2048, 8192]
    gemm_fp16<EPI_BIAS_GELU, true><<<dim3(INNER / 128, SEQ / 128), 256, GEMM_SMEM>>>(
        h1h, ff1h, ff1_b, nullptr, ff, SEQ, INNER, DMODEL);

    // 6) res2 = h1 + ff @ ff2_w + ff2_b  (fp32)
    gemm_fp16<EPI_BIAS_RES, false><<<dim3(DMODEL / 128, SEQ / 128), 256, GEMM_SMEM>>>(
        ff, ff2h, ff2_b, h1, res2, SEQ, DMODEL, INNER);

    // 7) out = LN2(res2)
    ln_kernel<<<SEQ, 256>>>(res2, ln2_g, ln2_b, out, nullptr);
}